// round 14
// baseline (speedup 1.0000x reference)
#include <cuda_runtime.h>
#include <math.h>

#define T_LEN 32768
#define AD 512
#define CCH 32
#define KF 31
#define DU 1024
#define EP 512
#define NBMID 1024
#define KC 2.8853900817779268f   // 2*log2(e)

// ---------------- scratch (device globals; no allocation) ----------------
__device__ float g_conv[CCH * T_LEN];
__device__ float g_dz[AD];
__device__ float g_epart[4 * T_LEN];
__device__ float g_q[T_LEN];
__device__ float g_p[T_LEN];
__device__ float g_partS[128];
__device__ float g_part2[NBMID];
__device__ float g_cpart[NBMID * EP];

__device__ __forceinline__ float ex2f(float x) {
    float r; asm("ex2.approx.f32 %0, %1;" : "=f"(r) : "f"(x)); return r;
}
__device__ __forceinline__ float rcpf(float x) {
    float r; asm("rcp.approx.f32 %0, %1;" : "=f"(r) : "f"(x)); return r;
}
__device__ __forceinline__ unsigned long long pk2(float a, float b) {
    unsigned long long r;
    asm("mov.b64 %0, {%1,%2};" : "=l"(r) : "f"(a), "f"(b));
    return r;
}
__device__ __forceinline__ float2 upk2(unsigned long long v) {
    float2 r;
    asm("mov.b64 {%0,%1}, %2;" : "=f"(r.x), "=f"(r.y) : "l"(v));
    return r;
}
__device__ __forceinline__ void fma2(unsigned long long& d, unsigned long long a,
                                     unsigned long long b) {
    asm("fma.rn.f32x2 %0, %1, %2, %0;" : "+l"(d) : "l"(a), "l"(b));
}

// ---------------- k_conv: 128 blocks x 256 t --------------------------------
__global__ __launch_bounds__(256) void k_conv(
        const float* __restrict__ ap, const float* __restrict__ cw,
        const float* __restrict__ cb) {
    __shared__ float apt[286];
    __shared__ float wsm[CCH * KF];
    __shared__ float wb[CCH];
    const int tid = threadIdx.x;
    const int t0 = blockIdx.x * 256;
    for (int i = tid; i < 286; i += 256) {
        int g = t0 - 15 + i;
        apt[i] = (g >= 0 && g < T_LEN) ? ap[g] : 0.f;
    }
    for (int i = tid; i < CCH * KF; i += 256) wsm[i] = cw[i];
    if (tid < CCH) wb[tid] = cb[tid];
    __syncthreads();

    float win[KF];
    #pragma unroll
    for (int f = 0; f < KF; f++) win[f] = apt[tid + f];

    #pragma unroll 2
    for (int c = 0; c < CCH; c++) {
        float acc = wb[c];
        #pragma unroll
        for (int f = 0; f < KF; f++) acc += win[f] * wsm[c * KF + f];
        g_conv[c * T_LEN + t0 + tid] = acc;
    }
}

// ---------------- k_dz: 32 blocks x 8 warps; inputs only -> full overlap ----
// gridDepSync at END only: keeps PDL chain transitive without stalling work.
__global__ __launch_bounds__(256) void k_dz(
        const float* __restrict__ dec_z, const float* __restrict__ W_dec, int base) {
    int warp = base + blockIdx.x * 8 + (threadIdx.x >> 5);
    int lane = threadIdx.x & 31;
    const float* row = W_dec + warp * DU;
    float acc = 0.f;
    #pragma unroll 4
    for (int k = lane; k < DU; k += 32) acc += row[k] * dec_z[k];
    #pragma unroll
    for (int o = 16; o; o >>= 1) acc += __shfl_xor_sync(0xffffffffu, acc, o);
    if (lane == 0) g_dz[warp] = acc;
    cudaGridDependencySynchronize();   // transitivity: don't complete before k_conv
}

// ---------------- k_e: fused proj-GEMM(f32x2, dup-W smem) + tanh + W_g dot --
// grid 2048 = 512 t-tiles x 4 a-quarters; 64 t x 128 a; thread tile 8t x 4a.
// W_att stored pre-duplicated (w,w) -> GEMM loop has ZERO pack MOVs.
// smem floats: cs[0,2048) wsd[2048,10496) dzs[10496,10624) wgs[10624,10752)
//            = 43008 B  -> (256,4): 32 warps/SM.
__global__ __launch_bounds__(256, 4) void k_e(
        const float* __restrict__ pre, const float* __restrict__ W_att,
        const float* __restrict__ W_g) {
    extern __shared__ float dyn[];
    float* cs   = dyn;                         // 32 x 64
    float2* wsd = (float2*)(dyn + 2048);       // 32 rows x 132 (pad) float2
    float* dzs  = dyn + 10496;                 // 128
    float* wgs  = dyn + 10624;                 // 128

    const int tid = threadIdx.x;
    const int tx = tid & 31;
    const int ty = tid >> 5;
    const int tb = blockIdx.x >> 2;
    const int q  = blockIdx.x & 3;
    const int t0 = tb * 64;
    const int a0 = q * 128;

    // PDL-early: stage input-only W_att (duplicated) and W_g
    for (int i = tid; i < 128 * 32; i += 256) {
        int al = i >> 5, c = i & 31;
        float w = W_att[(a0 + al) * 32 + c];
        wsd[c * 132 + al] = make_float2(w, w);
    }
    if (tid < 128) wgs[tid] = W_g[a0 + tid];

    cudaGridDependencySynchronize();   // wait for g_conv / g_dz

    for (int i = tid; i < CCH * 64; i += 256) {
        int c = i >> 6, tl = i & 63;
        cs[i] = g_conv[c * T_LEN + t0 + tl];
    }
    if (tid < 128) dzs[tid] = g_dz[a0 + tid];
    __syncthreads();

    // acc init = packed pre pairs (t-pair per 64-bit lane)
    unsigned long long acc[16];
    #pragma unroll
    for (int p = 0; p < 4; p++) {
        const size_t tA = (size_t)(t0 + ty * 8 + 2 * p) * AD + a0 + tx * 4;
        const float4 prA = __ldg((const float4*)(pre + tA));
        const float4 prB = __ldg((const float4*)(pre + tA + AD));
        acc[p * 4 + 0] = pk2(prA.x, prB.x);
        acc[p * 4 + 1] = pk2(prA.y, prB.y);
        acc[p * 4 + 2] = pk2(prA.z, prB.z);
        acc[p * 4 + 3] = pk2(prA.w, prB.w);
    }

    const unsigned long long* wsd_u = (const unsigned long long*)wsd;

    #pragma unroll
    for (int c = 0; c < 32; c++) {
        const ulonglong2 A = *(const ulonglong2*)(cs + c * 64 + ty * 8);
        const ulonglong2 B = *(const ulonglong2*)(cs + c * 64 + ty * 8 + 4);
        const unsigned long long* wp = wsd_u + c * 132 + tx * 4;
        const ulonglong2 W0 = *(const ulonglong2*)(wp);      // (w0,w0),(w1,w1)
        const ulonglong2 W1 = *(const ulonglong2*)(wp + 2);  // (w2,w2),(w3,w3)
        fma2(acc[0],  A.x, W0.x); fma2(acc[1],  A.x, W0.y);
        fma2(acc[2],  A.x, W1.x); fma2(acc[3],  A.x, W1.y);
        fma2(acc[4],  A.y, W0.x); fma2(acc[5],  A.y, W0.y);
        fma2(acc[6],  A.y, W1.x); fma2(acc[7],  A.y, W1.y);
        fma2(acc[8],  B.x, W0.x); fma2(acc[9],  B.x, W0.y);
        fma2(acc[10], B.x, W1.x); fma2(acc[11], B.x, W1.y);
        fma2(acc[12], B.y, W0.x); fma2(acc[13], B.y, W0.y);
        fma2(acc[14], B.y, W1.x); fma2(acc[15], B.y, W1.y);
    }

    float esum[8];
    #pragma unroll
    for (int i = 0; i < 8; i++) esum[i] = 0.f;

    const float4 d4 = ((const float4*)dzs)[tx];
    const float4 g4 = ((const float4*)wgs)[tx];
    float gsum = g4.x + g4.y + g4.z + g4.w;
    const float4 kd = make_float4(KC * d4.x, KC * d4.y, KC * d4.z, KC * d4.w);
    const float4 mg = make_float4(-2.f * g4.x, -2.f * g4.y,
                                  -2.f * g4.z, -2.f * g4.w);
    #pragma unroll
    for (int p = 0; p < 4; p++) {
        float2 p0 = upk2(acc[p * 4 + 0]);
        float2 p1 = upk2(acc[p * 4 + 1]);
        float2 p2 = upk2(acc[p * 4 + 2]);
        float2 p3 = upk2(acc[p * 4 + 3]);
        #pragma unroll
        for (int h = 0; h < 2; h++) {
            int i = p * 2 + h;
            float q0 = h ? p0.y : p0.x;
            float q1 = h ? p1.y : p1.x;
            float q2 = h ? p2.y : p2.x;
            float q3 = h ? p3.y : p3.x;
            float u0 = fmaf(KC, q0, kd.x);
            float u1 = fmaf(KC, q1, kd.y);
            float u2 = fmaf(KC, q2, kd.z);
            float u3 = fmaf(KC, q3, kd.w);
            float r0 = rcpf(ex2f(u0) + 1.f);
            float r1 = rcpf(ex2f(u1) + 1.f);
            float r2 = rcpf(ex2f(u2) + 1.f);
            float r3 = rcpf(ex2f(u3) + 1.f);
            esum[i] = fmaf(mg.x, r0, esum[i]);
            esum[i] = fmaf(mg.y, r1, esum[i]);
            esum[i] = fmaf(mg.z, r2, esum[i]);
            esum[i] = fmaf(mg.w, r3, esum[i]);
        }
    }

    #pragma unroll
    for (int o = 16; o; o >>= 1) gsum += __shfl_xor_sync(0xffffffffu, gsum, o);

    #pragma unroll
    for (int i = 0; i < 8; i++) {
        float v = esum[i];
        #pragma unroll
        for (int o = 16; o; o >>= 1) v += __shfl_xor_sync(0xffffffffu, v, o);
        if (tx == 0) {
            int t = t0 + ty * 8 + i;
            g_epart[q * T_LEN + t] = v + gsum;
        }
    }
}

// ------- k_exp: e = sum(ep0..3)+bg+mask; wexp = exp(2e) (no max-sub); q; S --
__global__ __launch_bounds__(256) void k_exp(
        const float* __restrict__ ap, const float* __restrict__ b_g,
        const float* __restrict__ mask) {
    __shared__ float sm[256];
    int t = blockIdx.x * 256 + threadIdx.x;
    float apv = ap[t];
    float apm = (t > 0) ? ap[t - 1] : 0.f;
    float mk  = mask[t];
    float bg  = __ldg(b_g);

    cudaGridDependencySynchronize();   // wait for g_epart

    float e = (g_epart[t] + g_epart[T_LEN + t])
            + (g_epart[2 * T_LEN + t] + g_epart[3 * T_LEN + t]) + bg + mk;
    float wexp = __expf(2.0f * e);     // |e| <~ 21 -> fits f32 w/o max-sub
    g_q[t] = (apv + apm) * wexp;
    sm[threadIdx.x] = wexp;
    __syncthreads();
    for (int s = 128; s; s >>= 1) {
        if (threadIdx.x < s) sm[threadIdx.x] += sm[threadIdx.x + s];
        __syncthreads();
    }
    if (threadIdx.x == 0) g_partS[blockIdx.x] = sm[0];
}

// ---------------- k_mid (validated 16.0us): 1024 blocks x 256 thr ----------
__global__ __launch_bounds__(256) void k_mid(const float* __restrict__ enc_h) {
    __shared__ float sm[128];
    __shared__ float psm[32];
    __shared__ float csum[EP];

    const int tid = threadIdx.x;
    const int t0 = blockIdx.x * 32;
    const int grp = tid >> 7;
    const int cw = tid & 127;

    // PDL: issue ALL 16 enc_h loads (input-only) before waiting on k_exp
    const float4* eh = (const float4*)(enc_h + (size_t)(t0 + grp * 16) * EP) + cw;
    float4 v[16];
    #pragma unroll
    for (int j = 0; j < 16; j++) v[j] = __ldg(eh + j * (EP / 4));

    cudaGridDependencySynchronize();   // wait for g_q / g_partS

    if (tid < 128) sm[tid] = g_partS[tid];
    __syncthreads();
    for (int s = 64; s; s >>= 1) {
        if (tid < s) sm[tid] += sm[tid + s];
        __syncthreads();
    }
    const float invS = __fdividef(1.0f, sm[0]);
    __syncthreads();

    if (tid < 32) {
        float p = fmaxf(g_q[t0 + tid] * invS, 1e-6f);
        g_p[t0 + tid] = p;
        psm[tid] = p;
        float w = p;
        #pragma unroll
        for (int o = 16; o; o >>= 1) w += __shfl_xor_sync(0xffffffffu, w, o);
        if (tid == 0) g_part2[blockIdx.x] = w;
    }
    __syncthreads();

    float4 acc0 = make_float4(0.f, 0.f, 0.f, 0.f);
    float4 acc1 = make_float4(0.f, 0.f, 0.f, 0.f);
    #pragma unroll
    for (int j = 0; j < 16; j++) {
        float w = psm[grp * 16 + j];
        float4& a = (j & 1) ? acc1 : acc0;
        a.x = fmaf(v[j].x, w, a.x);
        a.y = fmaf(v[j].y, w, a.y);
        a.z = fmaf(v[j].z, w, a.z);
        a.w = fmaf(v[j].w, w, a.w);
    }
    float4 acc = make_float4(acc0.x + acc1.x, acc0.y + acc1.y,
                             acc0.z + acc1.z, acc0.w + acc1.w);

    if (grp == 0) {
        csum[cw * 4 + 0] = acc.x; csum[cw * 4 + 1] = acc.y;
        csum[cw * 4 + 2] = acc.z; csum[cw * 4 + 3] = acc.w;
    }
    __syncthreads();
    if (grp == 1) {
        g_cpart[blockIdx.x * EP + cw * 4 + 0] = csum[cw * 4 + 0] + acc.x;
        g_cpart[blockIdx.x * EP + cw * 4 + 1] = csum[cw * 4 + 1] + acc.y;
        g_cpart[blockIdx.x * EP + cw * 4 + 2] = csum[cw * 4 + 2] + acc.z;
        g_cpart[blockIdx.x * EP + cw * 4 + 3] = csum[cw * 4 + 3] + acc.w;
    }
}

// ---------------- k_fin: w = p/sum2 ; c = (sum_b cpart)/sum2 ---------------
__global__ __launch_bounds__(512) void k_fin(float* __restrict__ out) {
    __shared__ float sm[512];
    __shared__ float cacc[512];
    const int tid = threadIdx.x;

    cudaGridDependencySynchronize();   // wait for g_p / g_part2 / g_cpart

    sm[tid] = g_part2[tid] + g_part2[tid + 512];
    __syncthreads();
    for (int s = 256; s; s >>= 1) {
        if (tid < s) sm[tid] += sm[tid + s];
        __syncthreads();
    }
    const float inv = __fdividef(1.0f, sm[0]);

    if (blockIdx.x < 64) {
        int t = blockIdx.x * 512 + tid;
        out[512 + t] = g_p[t] * inv;           // w
    } else {
        int cb = blockIdx.x - 64;
        int col = cb * 128 + (tid & 127);
        int seg = tid >> 7;
        float s = 0.f;
        #pragma unroll 8
        for (int k = seg * 256; k < seg * 256 + 256; k++)
            s += g_cpart[k * EP + col];
        cacc[tid] = s;
        __syncthreads();
        if (seg == 0)
            out[col] = (cacc[tid] + cacc[tid + 128] + cacc[tid + 256]
                        + cacc[tid + 384]) * inv;   // c
    }
}

// ---------------- launch (PDL on kernels 2..7) ----------------
template <typename F, typename... Args>
static inline void launch_pdl(F f, dim3 grid, dim3 block, size_t smem, Args... args) {
    cudaLaunchConfig_t cfg = {};
    cfg.gridDim = grid;
    cfg.blockDim = block;
    cfg.dynamicSmemBytes = smem;
    cfg.stream = 0;
    cudaLaunchAttribute attr[1];
    attr[0].id = cudaLaunchAttributeProgrammaticStreamSerialization;
    attr[0].val.programmaticStreamSerializationAllowed = 1;
    cfg.attrs = attr;
    cfg.numAttrs = 1;
    cudaLaunchKernelEx(&cfg, f, args...);
}

extern "C" void kernel_launch(void* const* d_in, const int* in_sizes, int n_in,
                              void* d_out, int out_size) {
    const float* dec_z    = (const float*)d_in[0];
    const float* att_prev = (const float*)d_in[1];
    const float* pre      = (const float*)d_in[2];
    const float* enc_h    = (const float*)d_in[3];
    const float* mask     = (const float*)d_in[4];
    const float* conv_w   = (const float*)d_in[5];
    const float* conv_b   = (const float*)d_in[6];
    const float* W_att    = (const float*)d_in[7];
    const float* W_dec    = (const float*)d_in[8];
    const float* W_g      = (const float*)d_in[9];
    const float* b_g      = (const float*)d_in[10];
    float* out = (float*)d_out;   // [0:512) = c, [512:512+T) = w

    const int ke_smem = 10752 * 4;   // 43008 B
    cudaFuncSetAttribute(k_e, cudaFuncAttributeMaxDynamicSharedMemorySize, ke_smem);
    cudaFuncSetAttribute(k_e, cudaFuncAttributePreferredSharedMemoryCarveout, 100);

    k_conv<<<128, 256>>>(att_prev, conv_w, conv_b);                        // 1
    launch_pdl(k_dz, dim3(32), dim3(256), (size_t)0, dec_z, W_dec, 0);     // 2 (overlaps 1)
    launch_pdl(k_dz, dim3(32), dim3(256), (size_t)0, dec_z, W_dec, 256);   // 3 (overlaps 1)
    launch_pdl(k_e, dim3(2048), dim3(256), (size_t)ke_smem, pre, W_att, W_g); // 4 (ncu slot)
    launch_pdl(k_exp, dim3(128), dim3(256), (size_t)0, att_prev, b_g, mask);  // 5
    launch_pdl(k_mid, dim3(NBMID), dim3(256), (size_t)0, enc_h);           // 6
    launch_pdl(k_fin, dim3(68), dim3(512), (size_t)0, out);                // 7
}

// round 15
// speedup vs baseline: 1.2771x; 1.2771x over previous
#include <cuda_runtime.h>
#include <math.h>

#define T_LEN 32768
#define AD 512
#define CCH 32
#define KF 31
#define DU 1024
#define EP 512
#define NBMID 1024
#define KC 2.8853900817779268f   // 2*log2(e)

// ---------------- scratch (device globals; no allocation) ----------------
__device__ float g_conv[CCH * T_LEN];
__device__ float g_dz[AD];
__device__ float g_epart[2 * T_LEN];
__device__ float g_q[T_LEN];
__device__ float g_p[T_LEN];
__device__ float g_partS[128];
__device__ float g_part2[NBMID];
__device__ float g_cpart[NBMID * EP];

__device__ __forceinline__ float ex2f(float x) {
    float r; asm("ex2.approx.f32 %0, %1;" : "=f"(r) : "f"(x)); return r;
}
__device__ __forceinline__ float rcpf(float x) {
    float r; asm("rcp.approx.f32 %0, %1;" : "=f"(r) : "f"(x)); return r;
}
__device__ __forceinline__ unsigned long long pk2(float a, float b) {
    unsigned long long r;
    asm("mov.b64 %0, {%1,%2};" : "=l"(r) : "f"(a), "f"(b));
    return r;
}
__device__ __forceinline__ float2 upk2(unsigned long long v) {
    float2 r;
    asm("mov.b64 {%0,%1}, %2;" : "=f"(r.x), "=f"(r.y) : "l"(v));
    return r;
}
__device__ __forceinline__ void fma2(unsigned long long& d, unsigned long long a,
                                     unsigned long long b) {
    asm("fma.rn.f32x2 %0, %1, %2, %0;" : "+l"(d) : "l"(a), "l"(b));
}

// ---------------- k_conv: 128 blocks x 256 t --------------------------------
__global__ __launch_bounds__(256) void k_conv(
        const float* __restrict__ ap, const float* __restrict__ cw,
        const float* __restrict__ cb) {
    __shared__ float apt[286];
    __shared__ float wsm[CCH * KF];
    __shared__ float wb[CCH];
    const int tid = threadIdx.x;
    const int t0 = blockIdx.x * 256;
    for (int i = tid; i < 286; i += 256) {
        int g = t0 - 15 + i;
        apt[i] = (g >= 0 && g < T_LEN) ? ap[g] : 0.f;
    }
    for (int i = tid; i < CCH * KF; i += 256) wsm[i] = cw[i];
    if (tid < CCH) wb[tid] = cb[tid];
    __syncthreads();

    float win[KF];
    #pragma unroll
    for (int f = 0; f < KF; f++) win[f] = apt[tid + f];

    #pragma unroll 2
    for (int c = 0; c < CCH; c++) {
        float acc = wb[c];
        #pragma unroll
        for (int f = 0; f < KF; f++) acc += win[f] * wsm[c * KF + f];
        g_conv[c * T_LEN + t0 + tid] = acc;
    }
}

// ---------------- k_dz: 32 blocks x 8 warps; inputs only -> overlaps k_conv -
__global__ __launch_bounds__(256) void k_dz(
        const float* __restrict__ dec_z, const float* __restrict__ W_dec, int base) {
    int warp = base + blockIdx.x * 8 + (threadIdx.x >> 5);
    int lane = threadIdx.x & 31;
    const float* row = W_dec + warp * DU;
    float acc = 0.f;
    #pragma unroll 4
    for (int k = lane; k < DU; k += 32) acc += row[k] * dec_z[k];
    #pragma unroll
    for (int o = 16; o; o >>= 1) acc += __shfl_xor_sync(0xffffffffu, acc, o);
    if (lane == 0) g_dz[warp] = acc;
    cudaGridDependencySynchronize();   // transitivity only
}

// ---------------- k_e (R9-validated cfg + pairwise rcp) ---------------------
// grid 1024 = 512 t-tiles x 2 a-halves; 64 t x 256 a; thread tile 8t x 4a.
__global__ __launch_bounds__(256, 3) void k_e(
        const float* __restrict__ pre, const float* __restrict__ W_att,
        const float* __restrict__ W_g) {
    extern __shared__ float dyn[];
    float* cs  = dyn;                  // 32*64
    float* ws  = dyn + 2048;           // 32*264
    float* dzs = ws + 32 * 264;        // 256
    float* wgs = dzs + 256;            // 256

    const int tid = threadIdx.x;
    const int tx = tid & 31;
    const int ty = tid >> 5;
    const int tb   = blockIdx.x >> 1;
    const int half = blockIdx.x & 1;
    const int t0 = tb * 64;
    const int a0 = half * 256;

    // PDL: stage input-only data (W_att, W_g) before waiting on conv/dz
    for (int i = tid; i < 256 * CCH; i += 256) {
        int al = i >> 5, c = i & 31;
        ws[c * 264 + al] = W_att[(a0 + al) * 32 + c];
    }
    for (int i = tid; i < 256; i += 256) wgs[i] = W_g[a0 + i];

    cudaGridDependencySynchronize();   // wait for g_conv / g_dz

    for (int i = tid; i < CCH * 64; i += 256) {
        int c = i >> 6, tl = i & 63;
        cs[i] = g_conv[c * T_LEN + t0 + tl];
    }
    for (int i = tid; i < 256; i += 256) dzs[i] = g_dz[a0 + i];
    __syncthreads();

    float esum[8];
    #pragma unroll
    for (int i = 0; i < 8; i++) esum[i] = 0.f;
    float gsum = 0.f;

    const float4* ws4 = (const float4*)ws;   // row stride 66 float4

    #pragma unroll 1
    for (int chunk = 0; chunk < 2; chunk++) {
        // acc init = packed pre pairs
        unsigned long long acc[16];
        #pragma unroll
        for (int p = 0; p < 4; p++) {
            const size_t tA = (size_t)(t0 + ty * 8 + 2 * p) * AD + a0 + chunk * 128 + tx * 4;
            const float4 prA = __ldg((const float4*)(pre + tA));
            const float4 prB = __ldg((const float4*)(pre + tA + AD));
            acc[p * 4 + 0] = pk2(prA.x, prB.x);
            acc[p * 4 + 1] = pk2(prA.y, prB.y);
            acc[p * 4 + 2] = pk2(prA.z, prB.z);
            acc[p * 4 + 3] = pk2(prA.w, prB.w);
        }

        #pragma unroll
        for (int c = 0; c < 32; c++) {
            const ulonglong2 A = *(const ulonglong2*)(cs + c * 64 + ty * 8);
            const ulonglong2 B = *(const ulonglong2*)(cs + c * 64 + ty * 8 + 4);
            const float4 w4 = ws4[c * 66 + chunk * 32 + tx];
            unsigned long long w0 = pk2(w4.x, w4.x), w1 = pk2(w4.y, w4.y);
            unsigned long long w2 = pk2(w4.z, w4.z), w3 = pk2(w4.w, w4.w);
            fma2(acc[0],  A.x, w0); fma2(acc[1],  A.x, w1);
            fma2(acc[2],  A.x, w2); fma2(acc[3],  A.x, w3);
            fma2(acc[4],  A.y, w0); fma2(acc[5],  A.y, w1);
            fma2(acc[6],  A.y, w2); fma2(acc[7],  A.y, w3);
            fma2(acc[8],  B.x, w0); fma2(acc[9],  B.x, w1);
            fma2(acc[10], B.x, w2); fma2(acc[11], B.x, w3);
            fma2(acc[12], B.y, w0); fma2(acc[13], B.y, w1);
            fma2(acc[14], B.y, w2); fma2(acc[15], B.y, w3);
        }

        const float4 d4 = ((const float4*)dzs)[chunk * 32 + tx];
        const float4 g4 = ((const float4*)wgs)[chunk * 32 + tx];
        gsum += g4.x + g4.y + g4.z + g4.w;
        const float4 kd = make_float4(KC * d4.x, KC * d4.y, KC * d4.z, KC * d4.w);
        const float4 mg = make_float4(-2.f * g4.x, -2.f * g4.y,
                                      -2.f * g4.z, -2.f * g4.w);
        #pragma unroll
        for (int p = 0; p < 4; p++) {
            float2 p0 = upk2(acc[p * 4 + 0]);
            float2 p1 = upk2(acc[p * 4 + 1]);
            float2 p2 = upk2(acc[p * 4 + 2]);
            float2 p3 = upk2(acc[p * 4 + 3]);
            #pragma unroll
            for (int h = 0; h < 2; h++) {
                int i = p * 2 + h;
                float q0 = h ? p0.y : p0.x;
                float q1 = h ? p1.y : p1.x;
                float q2 = h ? p2.y : p2.x;
                float q3 = h ? p3.y : p3.x;
                float u0 = fmaf(KC, q0, kd.x);
                float u1 = fmaf(KC, q1, kd.y);
                float u2 = fmaf(KC, q2, kd.z);
                float u3 = fmaf(KC, q3, kd.w);
                // pairwise reciprocal: 6 MUFU per group instead of 8
                float v0 = ex2f(u0) + 1.f;
                float v1 = ex2f(u1) + 1.f;
                float v2 = ex2f(u2) + 1.f;
                float v3 = ex2f(u3) + 1.f;
                float r01 = rcpf(v0 * v1);
                float r23 = rcpf(v2 * v3);
                float r0 = v1 * r01;
                float r1 = v0 * r01;
                float r2 = v3 * r23;
                float r3 = v2 * r23;
                esum[i] = fmaf(mg.x, r0, esum[i]);
                esum[i] = fmaf(mg.y, r1, esum[i]);
                esum[i] = fmaf(mg.z, r2, esum[i]);
                esum[i] = fmaf(mg.w, r3, esum[i]);
            }
        }
    }

    #pragma unroll
    for (int o = 16; o; o >>= 1) gsum += __shfl_xor_sync(0xffffffffu, gsum, o);

    #pragma unroll
    for (int i = 0; i < 8; i++) {
        float v = esum[i];
        #pragma unroll
        for (int o = 16; o; o >>= 1) v += __shfl_xor_sync(0xffffffffu, v, o);
        if (tx == 0) {
            int t = t0 + ty * 8 + i;
            g_epart[half * T_LEN + t] = v + gsum;
        }
    }
}

// ------- k_exp: e = ep0+ep1+bg+mask; wexp = exp(2e) (no max-sub); q; S -----
__global__ __launch_bounds__(256) void k_exp(
        const float* __restrict__ ap, const float* __restrict__ b_g,
        const float* __restrict__ mask) {
    __shared__ float sm[256];
    int t = blockIdx.x * 256 + threadIdx.x;
    float apv = ap[t];
    float apm = (t > 0) ? ap[t - 1] : 0.f;
    float mk  = mask[t];
    float bg  = __ldg(b_g);

    cudaGridDependencySynchronize();   // wait for g_epart

    float e = g_epart[t] + g_epart[T_LEN + t] + bg + mk;
    float wexp = __expf(2.0f * e);     // |e| <~ 21 -> fits f32 w/o max-sub
    g_q[t] = (apv + apm) * wexp;
    sm[threadIdx.x] = wexp;
    __syncthreads();
    for (int s = 128; s; s >>= 1) {
        if (threadIdx.x < s) sm[threadIdx.x] += sm[threadIdx.x + s];
        __syncthreads();
    }
    if (threadIdx.x == 0) g_partS[blockIdx.x] = sm[0];
}

// ---------------- k_mid (validated 15.7-16.0us): 1024 blocks x 256 thr -----
__global__ __launch_bounds__(256) void k_mid(const float* __restrict__ enc_h) {
    __shared__ float sm[128];
    __shared__ float psm[32];
    __shared__ float csum[EP];

    const int tid = threadIdx.x;
    const int t0 = blockIdx.x * 32;
    const int grp = tid >> 7;
    const int cw = tid & 127;

    // PDL: issue ALL 16 enc_h loads (input-only) before waiting on k_exp
    const float4* eh = (const float4*)(enc_h + (size_t)(t0 + grp * 16) * EP) + cw;
    float4 v[16];
    #pragma unroll
    for (int j = 0; j < 16; j++) v[j] = __ldg(eh + j * (EP / 4));

    cudaGridDependencySynchronize();   // wait for g_q / g_partS

    if (tid < 128) sm[tid] = g_partS[tid];
    __syncthreads();
    for (int s = 64; s; s >>= 1) {
        if (tid < s) sm[tid] += sm[tid + s];
        __syncthreads();
    }
    const float invS = __fdividef(1.0f, sm[0]);
    __syncthreads();

    if (tid < 32) {
        float p = fmaxf(g_q[t0 + tid] * invS, 1e-6f);
        g_p[t0 + tid] = p;
        psm[tid] = p;
        float w = p;
        #pragma unroll
        for (int o = 16; o; o >>= 1) w += __shfl_xor_sync(0xffffffffu, w, o);
        if (tid == 0) g_part2[blockIdx.x] = w;
    }
    __syncthreads();

    float4 acc0 = make_float4(0.f, 0.f, 0.f, 0.f);
    float4 acc1 = make_float4(0.f, 0.f, 0.f, 0.f);
    #pragma unroll
    for (int j = 0; j < 16; j++) {
        float w = psm[grp * 16 + j];
        float4& a = (j & 1) ? acc1 : acc0;
        a.x = fmaf(v[j].x, w, a.x);
        a.y = fmaf(v[j].y, w, a.y);
        a.z = fmaf(v[j].z, w, a.z);
        a.w = fmaf(v[j].w, w, a.w);
    }
    float4 acc = make_float4(acc0.x + acc1.x, acc0.y + acc1.y,
                             acc0.z + acc1.z, acc0.w + acc1.w);

    if (grp == 0) {
        csum[cw * 4 + 0] = acc.x; csum[cw * 4 + 1] = acc.y;
        csum[cw * 4 + 2] = acc.z; csum[cw * 4 + 3] = acc.w;
    }
    __syncthreads();
    if (grp == 1) {
        g_cpart[blockIdx.x * EP + cw * 4 + 0] = csum[cw * 4 + 0] + acc.x;
        g_cpart[blockIdx.x * EP + cw * 4 + 1] = csum[cw * 4 + 1] + acc.y;
        g_cpart[blockIdx.x * EP + cw * 4 + 2] = csum[cw * 4 + 2] + acc.z;
        g_cpart[blockIdx.x * EP + cw * 4 + 3] = csum[cw * 4 + 3] + acc.w;
    }
}

// ---------------- k_fin: w = p/sum2 ; c = (sum_b cpart)/sum2 ---------------
__global__ __launch_bounds__(512) void k_fin(float* __restrict__ out) {
    __shared__ float sm[512];
    __shared__ float cacc[512];
    const int tid = threadIdx.x;

    cudaGridDependencySynchronize();   // wait for g_p / g_part2 / g_cpart

    sm[tid] = g_part2[tid] + g_part2[tid + 512];
    __syncthreads();
    for (int s = 256; s; s >>= 1) {
        if (tid < s) sm[tid] += sm[tid + s];
        __syncthreads();
    }
    const float inv = __fdividef(1.0f, sm[0]);

    if (blockIdx.x < 64) {
        int t = blockIdx.x * 512 + tid;
        out[512 + t] = g_p[t] * inv;           // w
    } else {
        int cb = blockIdx.x - 64;
        int col = cb * 128 + (tid & 127);
        int seg = tid >> 7;
        float s = 0.f;
        #pragma unroll 8
        for (int k = seg * 256; k < seg * 256 + 256; k++)
            s += g_cpart[k * EP + col];
        cacc[tid] = s;
        __syncthreads();
        if (seg == 0)
            out[col] = (cacc[tid] + cacc[tid + 128] + cacc[tid + 256]
                        + cacc[tid + 384]) * inv;   // c
    }
}

// ---------------- launch (PDL on kernels 2..7) ----------------
template <typename F, typename... Args>
static inline void launch_pdl(F f, dim3 grid, dim3 block, size_t smem, Args... args) {
    cudaLaunchConfig_t cfg = {};
    cfg.gridDim = grid;
    cfg.blockDim = block;
    cfg.dynamicSmemBytes = smem;
    cfg.stream = 0;
    cudaLaunchAttribute attr[1];
    attr[0].id = cudaLaunchAttributeProgrammaticStreamSerialization;
    attr[0].val.programmaticStreamSerializationAllowed = 1;
    cfg.attrs = attr;
    cfg.numAttrs = 1;
    cudaLaunchKernelEx(&cfg, f, args...);
}

extern "C" void kernel_launch(void* const* d_in, const int* in_sizes, int n_in,
                              void* d_out, int out_size) {
    const float* dec_z    = (const float*)d_in[0];
    const float* att_prev = (const float*)d_in[1];
    const float* pre      = (const float*)d_in[2];
    const float* enc_h    = (const float*)d_in[3];
    const float* mask     = (const float*)d_in[4];
    const float* conv_w   = (const float*)d_in[5];
    const float* conv_b   = (const float*)d_in[6];
    const float* W_att    = (const float*)d_in[7];
    const float* W_dec    = (const float*)d_in[8];
    const float* W_g      = (const float*)d_in[9];
    const float* b_g      = (const float*)d_in[10];
    float* out = (float*)d_out;   // [0:512) = c, [512:512+T) = w

    const int ke_smem = (2048 + 32 * 264 + 256 + 256) * 4;   // 44032 B
    cudaFuncSetAttribute(k_e, cudaFuncAttributeMaxDynamicSharedMemorySize, ke_smem);

    k_conv<<<128, 256>>>(att_prev, conv_w, conv_b);                        // 1
    launch_pdl(k_dz, dim3(32), dim3(256), (size_t)0, dec_z, W_dec, 0);     // 2 (overlaps 1)
    launch_pdl(k_dz, dim3(32), dim3(256), (size_t)0, dec_z, W_dec, 256);   // 3 (overlaps 1)
    launch_pdl(k_e, dim3(1024), dim3(256), (size_t)ke_smem, pre, W_att, W_g); // 4 (ncu slot)
    launch_pdl(k_exp, dim3(128), dim3(256), (size_t)0, att_prev, b_g, mask);  // 5
    launch_pdl(k_mid, dim3(NBMID), dim3(256), (size_t)0, enc_h);           // 6
    launch_pdl(k_fin, dim3(68), dim3(512), (size_t)0, out);                // 7
}

// round 16
// speedup vs baseline: 1.4547x; 1.1391x over previous
#include <cuda_runtime.h>
#include <math.h>

#define T_LEN 32768
#define AD 512
#define CCH 32
#define KF 31
#define DU 1024
#define EP 512
#define NBMID 1024
#define KC 2.8853900817779268f   // 2*log2(e)

// ---------------- scratch (device globals; no allocation) ----------------
__device__ float g_conv[CCH * T_LEN];
__device__ float g_dz[AD];
__device__ float g_epart[2 * T_LEN];
__device__ float g_q[T_LEN];
__device__ float g_p[T_LEN];
__device__ float g_partS[128];
__device__ float g_part2[NBMID];
__device__ float g_cpart[NBMID * EP];

__device__ __forceinline__ float ex2f(float x) {
    float r; asm("ex2.approx.f32 %0, %1;" : "=f"(r) : "f"(x)); return r;
}
__device__ __forceinline__ float rcpf(float x) {
    float r; asm("rcp.approx.f32 %0, %1;" : "=f"(r) : "f"(x)); return r;
}
__device__ __forceinline__ unsigned long long pk2(float a, float b) {
    unsigned long long r;
    asm("mov.b64 %0, {%1,%2};" : "=l"(r) : "f"(a), "f"(b));
    return r;
}
__device__ __forceinline__ float2 upk2(unsigned long long v) {
    float2 r;
    asm("mov.b64 {%0,%1}, %2;" : "=f"(r.x), "=f"(r.y) : "l"(v));
    return r;
}
__device__ __forceinline__ void fma2(unsigned long long& d, unsigned long long a,
                                     unsigned long long b) {
    asm("fma.rn.f32x2 %0, %1, %2, %0;" : "+l"(d) : "l"(a), "l"(b));
}
__device__ __forceinline__ unsigned long long fma2n(unsigned long long a,
                                                    unsigned long long b,
                                                    unsigned long long c) {
    unsigned long long d;
    asm("fma.rn.f32x2 %0, %1, %2, %3;" : "=l"(d) : "l"(a), "l"(b), "l"(c));
    return d;
}

// ------- k_misc: conv (blocks 0..127) + dz GEMV (blocks 128..191) ----------
__global__ __launch_bounds__(256) void k_misc(
        const float* __restrict__ ap, const float* __restrict__ cw,
        const float* __restrict__ cb, const float* __restrict__ dec_z,
        const float* __restrict__ W_dec) {
    if (blockIdx.x < 128) {
        __shared__ float apt[286];
        __shared__ float wsm[CCH * KF];
        __shared__ float wb[CCH];
        const int tid = threadIdx.x;
        const int t0 = blockIdx.x * 256;
        for (int i = tid; i < 286; i += 256) {
            int g = t0 - 15 + i;
            apt[i] = (g >= 0 && g < T_LEN) ? ap[g] : 0.f;
        }
        for (int i = tid; i < CCH * KF; i += 256) wsm[i] = cw[i];
        if (tid < CCH) wb[tid] = cb[tid];
        __syncthreads();

        float win[KF];
        #pragma unroll
        for (int f = 0; f < KF; f++) win[f] = apt[tid + f];

        #pragma unroll 2
        for (int c = 0; c < CCH; c++) {
            float acc = wb[c];
            #pragma unroll
            for (int f = 0; f < KF; f++) acc += win[f] * wsm[c * KF + f];
            g_conv[c * T_LEN + t0 + tid] = acc;
        }
    } else {
        int warp = (blockIdx.x - 128) * 8 + (threadIdx.x >> 5);
        int lane = threadIdx.x & 31;
        const float* row = W_dec + warp * DU;
        float acc = 0.f;
        #pragma unroll 4
        for (int k = lane; k < DU; k += 32) acc += row[k] * dec_z[k];
        #pragma unroll
        for (int o = 16; o; o >>= 1) acc += __shfl_xor_sync(0xffffffffu, acc, o);
        if (lane == 0) g_dz[warp] = acc;
    }
}

// ---------------- k_e: fused proj-GEMM(f32x2) + tanh + W_g dot -------------
// R9-validated config; epilogue u computed packed (fma2) on t-pair accs.
__global__ __launch_bounds__(256, 3) void k_e(
        const float* __restrict__ pre, const float* __restrict__ W_att,
        const float* __restrict__ W_g) {
    extern __shared__ float dyn[];
    float* cs  = dyn;                  // 32*64
    float* ws  = dyn + 2048;           // 32*264
    float* dzs = ws + 32 * 264;        // 256
    float* wgs = dzs + 256;            // 256

    const int tid = threadIdx.x;
    const int tx = tid & 31;
    const int ty = tid >> 5;
    const int tb   = blockIdx.x >> 1;
    const int half = blockIdx.x & 1;
    const int t0 = tb * 64;
    const int a0 = half * 256;

    // PDL: stage input-only data (W_att, W_g) before waiting on k_misc
    for (int i = tid; i < 256 * CCH; i += 256) {
        int al = i >> 5, c = i & 31;
        ws[c * 264 + al] = W_att[(a0 + al) * 32 + c];
    }
    for (int i = tid; i < 256; i += 256) wgs[i] = W_g[a0 + i];

    cudaGridDependencySynchronize();   // wait for g_conv / g_dz

    for (int i = tid; i < CCH * 64; i += 256) {
        int c = i >> 6, tl = i & 63;
        cs[i] = g_conv[c * T_LEN + t0 + tl];
    }
    for (int i = tid; i < 256; i += 256) dzs[i] = g_dz[a0 + i];
    __syncthreads();

    float esum[8];
    #pragma unroll
    for (int i = 0; i < 8; i++) esum[i] = 0.f;
    float gsum = 0.f;

    const float4* ws4 = (const float4*)ws;   // row stride 66 float4
    const unsigned long long KCp = pk2(KC, KC);

    #pragma unroll 1
    for (int chunk = 0; chunk < 2; chunk++) {
        // acc init = packed pre pairs
        unsigned long long acc[16];
        #pragma unroll
        for (int p = 0; p < 4; p++) {
            const size_t tA = (size_t)(t0 + ty * 8 + 2 * p) * AD + a0 + chunk * 128 + tx * 4;
            const float4 prA = __ldg((const float4*)(pre + tA));
            const float4 prB = __ldg((const float4*)(pre + tA + AD));
            acc[p * 4 + 0] = pk2(prA.x, prB.x);
            acc[p * 4 + 1] = pk2(prA.y, prB.y);
            acc[p * 4 + 2] = pk2(prA.z, prB.z);
            acc[p * 4 + 3] = pk2(prA.w, prB.w);
        }

        #pragma unroll
        for (int c = 0; c < 32; c++) {
            const ulonglong2 A = *(const ulonglong2*)(cs + c * 64 + ty * 8);
            const ulonglong2 B = *(const ulonglong2*)(cs + c * 64 + ty * 8 + 4);
            const float4 w4 = ws4[c * 66 + chunk * 32 + tx];
            unsigned long long w0 = pk2(w4.x, w4.x), w1 = pk2(w4.y, w4.y);
            unsigned long long w2 = pk2(w4.z, w4.z), w3 = pk2(w4.w, w4.w);
            fma2(acc[0],  A.x, w0); fma2(acc[1],  A.x, w1);
            fma2(acc[2],  A.x, w2); fma2(acc[3],  A.x, w3);
            fma2(acc[4],  A.y, w0); fma2(acc[5],  A.y, w1);
            fma2(acc[6],  A.y, w2); fma2(acc[7],  A.y, w3);
            fma2(acc[8],  B.x, w0); fma2(acc[9],  B.x, w1);
            fma2(acc[10], B.x, w2); fma2(acc[11], B.x, w3);
            fma2(acc[12], B.y, w0); fma2(acc[13], B.y, w1);
            fma2(acc[14], B.y, w2); fma2(acc[15], B.y, w3);
        }

        const float4 d4 = ((const float4*)dzs)[chunk * 32 + tx];
        const float4 g4 = ((const float4*)wgs)[chunk * 32 + tx];
        gsum += g4.x + g4.y + g4.z + g4.w;
        // kd packed once per chunk: u2 = KC*acc + kd  (one fma2 per t-pair)
        const unsigned long long kdp0 = pk2(KC * d4.x, KC * d4.x);
        const unsigned long long kdp1 = pk2(KC * d4.y, KC * d4.y);
        const unsigned long long kdp2 = pk2(KC * d4.z, KC * d4.z);
        const unsigned long long kdp3 = pk2(KC * d4.w, KC * d4.w);
        const float4 mg = make_float4(-2.f * g4.x, -2.f * g4.y,
                                      -2.f * g4.z, -2.f * g4.w);
        #pragma unroll
        for (int p = 0; p < 4; p++) {
            float2 u0 = upk2(fma2n(KCp, acc[p * 4 + 0], kdp0));
            float2 u1 = upk2(fma2n(KCp, acc[p * 4 + 1], kdp1));
            float2 u2 = upk2(fma2n(KCp, acc[p * 4 + 2], kdp2));
            float2 u3 = upk2(fma2n(KCp, acc[p * 4 + 3], kdp3));
            #pragma unroll
            for (int h = 0; h < 2; h++) {
                int i = p * 2 + h;
                float r0 = rcpf(ex2f(h ? u0.y : u0.x) + 1.f);
                float r1 = rcpf(ex2f(h ? u1.y : u1.x) + 1.f);
                float r2 = rcpf(ex2f(h ? u2.y : u2.x) + 1.f);
                float r3 = rcpf(ex2f(h ? u3.y : u3.x) + 1.f);
                esum[i] = fmaf(mg.x, r0, esum[i]);
                esum[i] = fmaf(mg.y, r1, esum[i]);
                esum[i] = fmaf(mg.z, r2, esum[i]);
                esum[i] = fmaf(mg.w, r3, esum[i]);
            }
        }
    }

    #pragma unroll
    for (int o = 16; o; o >>= 1) gsum += __shfl_xor_sync(0xffffffffu, gsum, o);

    #pragma unroll
    for (int i = 0; i < 8; i++) {
        float v = esum[i];
        #pragma unroll
        for (int o = 16; o; o >>= 1) v += __shfl_xor_sync(0xffffffffu, v, o);
        if (tx == 0) {
            int t = t0 + ty * 8 + i;
            g_epart[half * T_LEN + t] = v + gsum;
        }
    }
}

// ------- k_exp: e = ep0+ep1+bg+mask; wexp = exp(2e) (no max-sub); q; S -----
__global__ __launch_bounds__(256) void k_exp(
        const float* __restrict__ ap, const float* __restrict__ b_g,
        const float* __restrict__ mask) {
    __shared__ float sm[256];
    int t = blockIdx.x * 256 + threadIdx.x;
    float apv = ap[t];
    float apm = (t > 0) ? ap[t - 1] : 0.f;
    float mk  = mask[t];
    float bg  = __ldg(b_g);

    cudaGridDependencySynchronize();   // wait for g_epart

    float e = g_epart[t] + g_epart[T_LEN + t] + bg + mk;
    float wexp = __expf(2.0f * e);     // |e| <~ 21 -> fits f32 w/o max-sub
    g_q[t] = (apv + apm) * wexp;
    sm[threadIdx.x] = wexp;
    __syncthreads();
    for (int s = 128; s; s >>= 1) {
        if (threadIdx.x < s) sm[threadIdx.x] += sm[threadIdx.x + s];
        __syncthreads();
    }
    if (threadIdx.x == 0) g_partS[blockIdx.x] = sm[0];
}

// ---------------- k_mid (validated 15.7us): 1024 blocks x 256 thr ----------
__global__ __launch_bounds__(256) void k_mid(const float* __restrict__ enc_h) {
    __shared__ float sm[128];
    __shared__ float psm[32];
    __shared__ float csum[EP];

    const int tid = threadIdx.x;
    const int t0 = blockIdx.x * 32;
    const int grp = tid >> 7;
    const int cw = tid & 127;

    // PDL: issue ALL 16 enc_h loads (input-only) before waiting on k_exp
    const float4* eh = (const float4*)(enc_h + (size_t)(t0 + grp * 16) * EP) + cw;
    float4 v[16];
    #pragma unroll
    for (int j = 0; j < 16; j++) v[j] = __ldg(eh + j * (EP / 4));

    cudaGridDependencySynchronize();   // wait for g_q / g_partS

    if (tid < 128) sm[tid] = g_partS[tid];
    __syncthreads();
    for (int s = 64; s; s >>= 1) {
        if (tid < s) sm[tid] += sm[tid + s];
        __syncthreads();
    }
    const float invS = __fdividef(1.0f, sm[0]);
    __syncthreads();

    if (tid < 32) {
        float p = fmaxf(g_q[t0 + tid] * invS, 1e-6f);
        g_p[t0 + tid] = p;
        psm[tid] = p;
        float w = p;
        #pragma unroll
        for (int o = 16; o; o >>= 1) w += __shfl_xor_sync(0xffffffffu, w, o);
        if (tid == 0) g_part2[blockIdx.x] = w;
    }
    __syncthreads();

    float4 acc0 = make_float4(0.f, 0.f, 0.f, 0.f);
    float4 acc1 = make_float4(0.f, 0.f, 0.f, 0.f);
    #pragma unroll
    for (int j = 0; j < 16; j++) {
        float w = psm[grp * 16 + j];
        float4& a = (j & 1) ? acc1 : acc0;
        a.x = fmaf(v[j].x, w, a.x);
        a.y = fmaf(v[j].y, w, a.y);
        a.z = fmaf(v[j].z, w, a.z);
        a.w = fmaf(v[j].w, w, a.w);
    }
    float4 acc = make_float4(acc0.x + acc1.x, acc0.y + acc1.y,
                             acc0.z + acc1.z, acc0.w + acc1.w);

    if (grp == 0) {
        csum[cw * 4 + 0] = acc.x; csum[cw * 4 + 1] = acc.y;
        csum[cw * 4 + 2] = acc.z; csum[cw * 4 + 3] = acc.w;
    }
    __syncthreads();
    if (grp == 1) {
        g_cpart[blockIdx.x * EP + cw * 4 + 0] = csum[cw * 4 + 0] + acc.x;
        g_cpart[blockIdx.x * EP + cw * 4 + 1] = csum[cw * 4 + 1] + acc.y;
        g_cpart[blockIdx.x * EP + cw * 4 + 2] = csum[cw * 4 + 2] + acc.z;
        g_cpart[blockIdx.x * EP + cw * 4 + 3] = csum[cw * 4 + 3] + acc.w;
    }
}

// ---------------- k_fin: w = p/sum2 ; c = (sum_b cpart)/sum2 ---------------
__global__ __launch_bounds__(512) void k_fin(float* __restrict__ out) {
    __shared__ float sm[512];
    __shared__ float cacc[512];
    const int tid = threadIdx.x;

    cudaGridDependencySynchronize();   // wait for g_p / g_part2 / g_cpart

    sm[tid] = g_part2[tid] + g_part2[tid + 512];
    __syncthreads();
    for (int s = 256; s; s >>= 1) {
        if (tid < s) sm[tid] += sm[tid + s];
        __syncthreads();
    }
    const float inv = __fdividef(1.0f, sm[0]);

    if (blockIdx.x < 64) {
        int t = blockIdx.x * 512 + tid;
        out[512 + t] = g_p[t] * inv;           // w
    } else {
        int cb = blockIdx.x - 64;
        int col = cb * 128 + (tid & 127);
        int seg = tid >> 7;
        float s = 0.f;
        #pragma unroll 8
        for (int k = seg * 256; k < seg * 256 + 256; k++)
            s += g_cpart[k * EP + col];
        cacc[tid] = s;
        __syncthreads();
        if (seg == 0)
            out[col] = (cacc[tid] + cacc[tid + 128] + cacc[tid + 256]
                        + cacc[tid + 384]) * inv;   // c
    }
}

// ---------------- launch (PDL on kernels 2..5) ----------------
template <typename F, typename... Args>
static inline void launch_pdl(F f, dim3 grid, dim3 block, size_t smem, Args... args) {
    cudaLaunchConfig_t cfg = {};
    cfg.gridDim = grid;
    cfg.blockDim = block;
    cfg.dynamicSmemBytes = smem;
    cfg.stream = 0;
    cudaLaunchAttribute attr[1];
    attr[0].id = cudaLaunchAttributeProgrammaticStreamSerialization;
    attr[0].val.programmaticStreamSerializationAllowed = 1;
    cfg.attrs = attr;
    cfg.numAttrs = 1;
    cudaLaunchKernelEx(&cfg, f, args...);
}

extern "C" void kernel_launch(void* const* d_in, const int* in_sizes, int n_in,
                              void* d_out, int out_size) {
    const float* dec_z    = (const float*)d_in[0];
    const float* att_prev = (const float*)d_in[1];
    const float* pre      = (const float*)d_in[2];
    const float* enc_h    = (const float*)d_in[3];
    const float* mask     = (const float*)d_in[4];
    const float* conv_w   = (const float*)d_in[5];
    const float* conv_b   = (const float*)d_in[6];
    const float* W_att    = (const float*)d_in[7];
    const float* W_dec    = (const float*)d_in[8];
    const float* W_g      = (const float*)d_in[9];
    const float* b_g      = (const float*)d_in[10];
    float* out = (float*)d_out;   // [0:512) = c, [512:512+T) = w

    const int ke_smem = (2048 + 32 * 264 + 256 + 256) * 4;   // 44032 B
    cudaFuncSetAttribute(k_e, cudaFuncAttributeMaxDynamicSharedMemorySize, ke_smem);

    k_misc<<<192, 256>>>(att_prev, conv_w, conv_b, dec_z, W_dec);      // 1
    launch_pdl(k_e, dim3(1024), dim3(256), (size_t)ke_smem, pre, W_att, W_g); // 2
    launch_pdl(k_exp, dim3(128), dim3(256), (size_t)0, att_prev, b_g, mask);  // 3
    launch_pdl(k_mid, dim3(NBMID), dim3(256), (size_t)0, enc_h);       // 4 (ncu slot)
    launch_pdl(k_fin, dim3(68), dim3(512), (size_t)0, out);            // 5
}